// round 4
// baseline (speedup 1.0000x reference)
#include <cuda_runtime.h>
#include <cuda_bf16.h>
#include <cstdint>

// Problem constants (fixed shapes)
#define BB 8192
#define DD 256
#define KK 64

// ---------------- scratch (static device arrays; no allocation) ----------------
__device__ __nv_bfloat16 g_Xbf[BB * DD];          // 4 MB
__device__ __nv_bfloat16 g_Sbf[KK * DD * DD];     // 8.4 MB
__device__ float         g_logits[BB * KK];       // 2 MB
__device__ float         g_contrib[KK * BB];      // 2 MB

// ---------------- helpers ----------------
__device__ __forceinline__ uint32_t smem_to_u32(const void* p) {
    uint32_t a;
    asm("{ .reg .u64 t; cvta.to.shared.u64 t, %1; cvt.u32.u64 %0, t; }" : "=r"(a) : "l"(p));
    return a;
}

__device__ __forceinline__ void cp_async16(uint32_t dst, const void* src) {
    asm volatile("cp.async.cg.shared.global [%0], [%1], 16;" :: "r"(dst), "l"(src));
}
#define CP_COMMIT() asm volatile("cp.async.commit_group;" ::: "memory")
#define CP_WAIT(n)  asm volatile("cp.async.wait_group %0;" :: "n"(n) : "memory")

__device__ __forceinline__ void ldsm_x4(uint32_t& r0, uint32_t& r1, uint32_t& r2, uint32_t& r3,
                                        uint32_t addr) {
    asm volatile("ldmatrix.sync.aligned.m8n8.x4.shared.b16 {%0,%1,%2,%3}, [%4];"
                 : "=r"(r0), "=r"(r1), "=r"(r2), "=r"(r3) : "r"(addr));
}

__device__ __forceinline__ void mma_bf16(float* d, const uint32_t* a, uint32_t b0, uint32_t b1) {
    asm volatile(
        "mma.sync.aligned.m16n8k16.row.col.f32.bf16.bf16.f32 "
        "{%0,%1,%2,%3}, {%4,%5,%6,%7}, {%8,%9}, {%0,%1,%2,%3};"
        : "+f"(d[0]), "+f"(d[1]), "+f"(d[2]), "+f"(d[3])
        : "r"(a[0]), "r"(a[1]), "r"(a[2]), "r"(a[3]), "r"(b0), "r"(b1));
}

// ---------------- kernel 1: fused fp32 -> bf16 converts (X then Sigma) ----------------
#define NX4 (BB * DD / 4)              // 524288 float4s for X
#define NS4 (KK * DD * DD / 4)         // 1048576 float4s for Sigma
__global__ void conv_kernel(const float4* __restrict__ xsrc, const float4* __restrict__ ssrc) {
    int i = blockIdx.x * blockDim.x + threadIdx.x;
    if (i < NX4) {
        float4 v = xsrc[i];
        __nv_bfloat162* dst = reinterpret_cast<__nv_bfloat162*>(g_Xbf);
        dst[2 * i]     = __floats2bfloat162_rn(v.x, v.y);
        dst[2 * i + 1] = __floats2bfloat162_rn(v.z, v.w);
    } else if (i < NX4 + NS4) {
        int j = i - NX4;
        float4 v = ssrc[j];
        __nv_bfloat162* dst = reinterpret_cast<__nv_bfloat162*>(g_Sbf);
        dst[2 * j]     = __floats2bfloat162_rn(v.x, v.y);
        dst[2 * j + 1] = __floats2bfloat162_rn(v.z, v.w);
    }
}

// ---------------- kernel 2: logits = X @ mu (fp32, exact) ----------------
#define LOGITS_SMEM ((128 * 257 + 256 * 64) * 4)
__global__ void logits_kernel(const float* __restrict__ X, const float* __restrict__ mu) {
    extern __shared__ float sm[];
    float* xs  = sm;                // [128][257] padded
    float* mus = sm + 128 * 257;    // [256][64]
    int t = threadIdx.x;
    int b0 = blockIdx.x * 128;

    const float4* xg = reinterpret_cast<const float4*>(X + (size_t)b0 * DD);
    #pragma unroll
    for (int j = 0; j < 32; j++) {
        int i = t + j * 256;
        float4 v = xg[i];
        int r = i >> 6, c = (i & 63) << 2;
        float* p = xs + r * 257 + c;
        p[0] = v.x; p[1] = v.y; p[2] = v.z; p[3] = v.w;
    }
    const float4* mg = reinterpret_cast<const float4*>(mu);
    float4* ms4 = reinterpret_cast<float4*>(mus);
    #pragma unroll
    for (int j = 0; j < 16; j++) ms4[t + j * 256] = mg[t + j * 256];
    __syncthreads();

    int r = t & 127;
    int kh = (t >> 7) * 32;
    float acc[32];
    #pragma unroll
    for (int kk = 0; kk < 32; kk++) acc[kk] = 0.f;
    const float* xr = xs + r * 257;
    for (int d = 0; d < DD; d++) {
        float xv = xr[d];
        const float* mrow = mus + d * 64 + kh;
        #pragma unroll
        for (int kk = 0; kk < 32; kk++) acc[kk] = fmaf(xv, mrow[kk], acc[kk]);
    }
    float* og = g_logits + (size_t)(b0 + r) * KK + kh;
    #pragma unroll
    for (int kk = 0; kk < 32; kk++) og[kk] = acc[kk];
}

// ---------------- kernel 3: main bf16 mma.sync GEMM + loss epilogue ----------------
// grid (64 b-tiles, 64 k), 256 threads (8 warps).
// Y[i,e] = sum_d X[b0+i,d] * Sigma[k,e,d]; xSx[i] = sum_e Y[i,e]*x[i,e]
// Warp tile m64 x n64 (MAC/LDS-byte = 16 vs 10.7 before); CTA tile 128x256.
// Kdim=256 in 4 chunks of 64, double-buffered cp.async.
#define SMA0 0
#define SMA1 16384
#define SMB0 32768
#define SMB1 65536
#define SMRED 98304
#define GEMM_SMEM (98304 + 2048)

__global__ void __launch_bounds__(256, 1)
gemm_loss_kernel(const int* __restrict__ y) {
    extern __shared__ char smem[];
    uint32_t sb = smem_to_u32(smem);
    const uint32_t A_off[2] = {SMA0, SMA1};
    const uint32_t B_off[2] = {SMB0, SMB1};
    float* red = reinterpret_cast<float*>(smem + SMRED);

    int tid = threadIdx.x, wid = tid >> 5, lid = tid & 31;
    int bt = blockIdx.x, k = blockIdx.y;
    int b0 = bt * 128;
    int mg = wid >> 2, ng = wid & 3;   // warp tile: rows mg*64..+63, cols ng*64..+63

    const char* Abase = reinterpret_cast<const char*>(g_Xbf) + (size_t)b0 * 512;
    const char* Bbase = reinterpret_cast<const char*>(g_Sbf) + (size_t)k * 131072;

    // ---- issue chunk 0 loads ----
    {
        #pragma unroll
        for (int j = 0; j < 4; j++) {     // A: 1024 x 16B granules
            int i = tid + j * 256;
            int row = i >> 3, cb = (i & 7) * 16;
            uint32_t dst = sb + A_off[0] + row * 128 + (cb ^ ((row & 7) << 4));
            cp_async16(dst, Abase + (size_t)row * 512 + cb);
        }
        #pragma unroll
        for (int j = 0; j < 8; j++) {     // B: 2048 x 16B granules
            int i = tid + j * 256;
            int row = i >> 3, cb = (i & 7) * 16;
            uint32_t dst = sb + B_off[0] + row * 128 + (cb ^ ((row & 7) << 4));
            cp_async16(dst, Bbase + (size_t)row * 512 + cb);
        }
        CP_COMMIT();
    }

    float acc[4][8][4];
    #pragma unroll
    for (int m = 0; m < 4; m++)
        #pragma unroll
        for (int n = 0; n < 8; n++)
            #pragma unroll
            for (int f = 0; f < 4; f++) acc[m][n][f] = 0.f;

    int lrow = lid & 15;
    int lcb16 = (lid >> 4) * 16;

    #pragma unroll
    for (int c = 0; c < 4; c++) {
        int buf = c & 1;
        if (c < 3) {
            int nb = (c + 1) & 1;
            #pragma unroll
            for (int j = 0; j < 4; j++) {
                int i = tid + j * 256;
                int row = i >> 3, cb = (i & 7) * 16;
                uint32_t dst = sb + A_off[nb] + row * 128 + (cb ^ ((row & 7) << 4));
                cp_async16(dst, Abase + (size_t)row * 512 + (c + 1) * 128 + cb);
            }
            #pragma unroll
            for (int j = 0; j < 8; j++) {
                int i = tid + j * 256;
                int row = i >> 3, cb = (i & 7) * 16;
                uint32_t dst = sb + B_off[nb] + row * 128 + (cb ^ ((row & 7) << 4));
                cp_async16(dst, Bbase + (size_t)row * 512 + (c + 1) * 128 + cb);
            }
            CP_COMMIT();
            CP_WAIT(1);
        } else {
            CP_WAIT(0);
        }
        __syncthreads();

        #pragma unroll
        for (int ks = 0; ks < 4; ks++) {
            int kb = ks * 32 + lcb16;        // byte col within 128B chunk row
            // B fragments: 4 n16 groups
            uint32_t bf[4][4];
            #pragma unroll
            for (int g = 0; g < 4; g++) {
                int row = ng * 64 + g * 16 + lrow;
                uint32_t addr = sb + B_off[buf] + row * 128 + (kb ^ ((row & 7) << 4));
                ldsm_x4(bf[g][0], bf[g][1], bf[g][2], bf[g][3], addr);
            }
            // A fragments: 4 m16 tiles, consumed as loaded
            #pragma unroll
            for (int m = 0; m < 4; m++) {
                uint32_t a[4];
                int row = mg * 64 + m * 16 + lrow;
                uint32_t addr = sb + A_off[buf] + row * 128 + (kb ^ ((row & 7) << 4));
                ldsm_x4(a[0], a[1], a[2], a[3], addr);
                #pragma unroll
                for (int g = 0; g < 4; g++) {
                    mma_bf16(acc[m][g * 2 + 0], a, bf[g][0], bf[g][2]);
                    mma_bf16(acc[m][g * 2 + 1], a, bf[g][1], bf[g][3]);
                }
            }
        }
        __syncthreads();
    }

    // ---- epilogue: dot rows of Y with x, reduce ----
    int gq = lid >> 2;           // row within m16 tile (0..7)
    int cq = (lid & 3) * 2;      // col pair base
    #pragma unroll
    for (int m = 0; m < 4; m++) {
        float rs0 = 0.f, rs1 = 0.f;
        int r0 = b0 + mg * 64 + m * 16 + gq;
        int r1 = r0 + 8;
        const __nv_bfloat162* x0 = reinterpret_cast<const __nv_bfloat162*>(g_Xbf + (size_t)r0 * 256);
        const __nv_bfloat162* x1 = reinterpret_cast<const __nv_bfloat162*>(g_Xbf + (size_t)r1 * 256);
        #pragma unroll
        for (int nt = 0; nt < 8; nt++) {
            int e = ng * 64 + nt * 8 + cq;
            float2 v0 = __bfloat1622float2(x0[e >> 1]);
            float2 v1 = __bfloat1622float2(x1[e >> 1]);
            rs0 = fmaf(acc[m][nt][0], v0.x, fmaf(acc[m][nt][1], v0.y, rs0));
            rs1 = fmaf(acc[m][nt][2], v1.x, fmaf(acc[m][nt][3], v1.y, rs1));
        }
        // quad reduce (lanes lid&~3..+3 share the same rows)
        rs0 += __shfl_xor_sync(0xFFFFFFFF, rs0, 1);
        rs0 += __shfl_xor_sync(0xFFFFFFFF, rs0, 2);
        rs1 += __shfl_xor_sync(0xFFFFFFFF, rs1, 1);
        rs1 += __shfl_xor_sync(0xFFFFFFFF, rs1, 2);
        if ((lid & 3) == 0) {
            int rr = mg * 64 + m * 16 + gq;
            red[rr * 4 + ng]       = rs0;
            red[(rr + 8) * 4 + ng] = rs1;
        }
    }
    __syncthreads();

    if (tid < 128) {
        int row = tid;
        float4 rv = reinterpret_cast<const float4*>(red)[row];
        float xsx = (rv.x + rv.y) + (rv.z + rv.w);
        int b = b0 + row;
        float l = g_logits[(size_t)b * KK + k];
        int yv = y[b];
        float psi = sqrtf(fmaxf(xsx, 0.f) + l * l);
        float bk  = (k <= yv) ? 1.f : 0.f;
        float kap = ((k == yv) ? 1.f : 0.f) - 0.5f * bk;
        float sp  = psi + log1pf(__expf(-psi));     // softplus(psi), psi >= 0
        g_contrib[(size_t)k * BB + b] = l * kap + bk * (0.5f * psi - sp);
    }
}

// ---------------- kernel 4: deterministic reduce over k ----------------
__global__ void reduce_kernel(float* __restrict__ out) {
    int b = blockIdx.x * blockDim.x + threadIdx.x;
    if (b < BB) {
        float s = 0.f;
        #pragma unroll 8
        for (int k = 0; k < KK; k++) s += g_contrib[(size_t)k * BB + b];
        out[b] = -s;
    }
}

// ---------------- launch ----------------
extern "C" void kernel_launch(void* const* d_in, const int* in_sizes, int n_in,
                              void* d_out, int out_size) {
    (void)in_sizes; (void)n_in; (void)out_size;
    const float* features = (const float*)d_in[0];
    const int*   y        = (const int*)d_in[1];
    const float* mu       = (const float*)d_in[2];
    const float* Sigma    = (const float*)d_in[3];
    float* out = (float*)d_out;

    cudaFuncSetAttribute(logits_kernel,    cudaFuncAttributeMaxDynamicSharedMemorySize, LOGITS_SMEM);
    cudaFuncSetAttribute(gemm_loss_kernel, cudaFuncAttributeMaxDynamicSharedMemorySize, GEMM_SMEM);

    conv_kernel<<<(NX4 + NS4 + 255) / 256, 256>>>(
        reinterpret_cast<const float4*>(features),
        reinterpret_cast<const float4*>(Sigma));
    logits_kernel<<<BB / 128, 256, LOGITS_SMEM>>>(features, mu);
    dim3 grid(BB / 128, KK);
    gemm_loss_kernel<<<grid, 256, GEMM_SMEM>>>(y);
    reduce_kernel<<<BB / 256, 256>>>(out);
}

// round 5
// speedup vs baseline: 1.1227x; 1.1227x over previous
#include <cuda_runtime.h>
#include <cuda_bf16.h>
#include <cstdint>

// Problem constants (fixed shapes)
#define BB 8192
#define DD 256
#define KK 64
#define KPC 2            // k's per CTA
#define QPC (KPC * 4)    // quarters per CTA (4 e-quarters per k)

// ---------------- scratch (static device arrays; no allocation) ----------------
__device__ __nv_bfloat16 g_Xbf[BB * DD];          // 4 MB
__device__ __nv_bfloat16 g_Sbf[KK * DD * DD];     // 8.4 MB
__device__ float         g_logits[BB * KK];       // 2 MB
__device__ float         g_contrib[(KK / KPC) * BB];  // 1 MB (32 slices)

// ---------------- helpers ----------------
__device__ __forceinline__ uint32_t smem_to_u32(const void* p) {
    uint32_t a;
    asm("{ .reg .u64 t; cvta.to.shared.u64 t, %1; cvt.u32.u64 %0, t; }" : "=r"(a) : "l"(p));
    return a;
}

__device__ __forceinline__ void cp_async16(uint32_t dst, const void* src) {
    asm volatile("cp.async.cg.shared.global [%0], [%1], 16;" :: "r"(dst), "l"(src));
}
#define CP_COMMIT() asm volatile("cp.async.commit_group;" ::: "memory")
#define CP_WAIT(n)  asm volatile("cp.async.wait_group %0;" :: "n"(n) : "memory")

__device__ __forceinline__ void ldsm_x4(uint32_t& r0, uint32_t& r1, uint32_t& r2, uint32_t& r3,
                                        uint32_t addr) {
    asm volatile("ldmatrix.sync.aligned.m8n8.x4.shared.b16 {%0,%1,%2,%3}, [%4];"
                 : "=r"(r0), "=r"(r1), "=r"(r2), "=r"(r3) : "r"(addr));
}

__device__ __forceinline__ void mma_bf16(float* d, const uint32_t* a, uint32_t b0, uint32_t b1) {
    asm volatile(
        "mma.sync.aligned.m16n8k16.row.col.f32.bf16.bf16.f32 "
        "{%0,%1,%2,%3}, {%4,%5,%6,%7}, {%8,%9}, {%0,%1,%2,%3};"
        : "+f"(d[0]), "+f"(d[1]), "+f"(d[2]), "+f"(d[3])
        : "r"(a[0]), "r"(a[1]), "r"(a[2]), "r"(a[3]), "r"(b0), "r"(b1));
}

// ---------------- kernel 1: fused fp32 -> bf16 converts (X then Sigma) ----------------
#define NX4 (BB * DD / 4)              // 524288 float4s for X
#define NS4 (KK * DD * DD / 4)         // 1048576 float4s for Sigma
__global__ void conv_kernel(const float4* __restrict__ xsrc, const float4* __restrict__ ssrc) {
    int i = blockIdx.x * blockDim.x + threadIdx.x;
    if (i < NX4) {
        float4 v = xsrc[i];
        __nv_bfloat162* dst = reinterpret_cast<__nv_bfloat162*>(g_Xbf);
        dst[2 * i]     = __floats2bfloat162_rn(v.x, v.y);
        dst[2 * i + 1] = __floats2bfloat162_rn(v.z, v.w);
    } else if (i < NX4 + NS4) {
        int j = i - NX4;
        float4 v = ssrc[j];
        __nv_bfloat162* dst = reinterpret_cast<__nv_bfloat162*>(g_Sbf);
        dst[2 * j]     = __floats2bfloat162_rn(v.x, v.y);
        dst[2 * j + 1] = __floats2bfloat162_rn(v.z, v.w);
    }
}

// ---------------- kernel 2: logits = X @ mu (fp32, exact) ----------------
#define LOGITS_SMEM ((128 * 257 + 256 * 64) * 4)
__global__ void logits_kernel(const float* __restrict__ X, const float* __restrict__ mu) {
    extern __shared__ float sm[];
    float* xs  = sm;                // [128][257] padded
    float* mus = sm + 128 * 257;    // [256][64]
    int t = threadIdx.x;
    int b0 = blockIdx.x * 128;

    const float4* xg = reinterpret_cast<const float4*>(X + (size_t)b0 * DD);
    #pragma unroll
    for (int j = 0; j < 32; j++) {
        int i = t + j * 256;
        float4 v = xg[i];
        int r = i >> 6, c = (i & 63) << 2;
        float* p = xs + r * 257 + c;
        p[0] = v.x; p[1] = v.y; p[2] = v.z; p[3] = v.w;
    }
    const float4* mg = reinterpret_cast<const float4*>(mu);
    float4* ms4 = reinterpret_cast<float4*>(mus);
    #pragma unroll
    for (int j = 0; j < 16; j++) ms4[t + j * 256] = mg[t + j * 256];
    __syncthreads();

    int r = t & 127;
    int kh = (t >> 7) * 32;
    float acc[32];
    #pragma unroll
    for (int kk = 0; kk < 32; kk++) acc[kk] = 0.f;
    const float* xr = xs + r * 257;
    for (int d = 0; d < DD; d++) {
        float xv = xr[d];
        const float* mrow = mus + d * 64 + kh;
        #pragma unroll
        for (int kk = 0; kk < 32; kk++) acc[kk] = fmaf(xv, mrow[kk], acc[kk]);
    }
    float* og = g_logits + (size_t)(b0 + r) * KK + kh;
    #pragma unroll
    for (int kk = 0; kk < 32; kk++) og[kk] = acc[kk];
}

// ---------------- kernel 3: main GEMM (A in registers, B quarter-ring) + loss ----------------
// grid (32 b-tiles, 32 kg), 256 threads (8 warps, each warp m32 over ALL e).
// Per CTA: 256 batch rows, 2 k's. B (Sigma_k) streamed in 32KB quarters (64 e-rows x 256 d),
// 3-deep cp.async ring. A fragments held in registers (128/thread), filled by LDG once.
// Contraction weights x[i,e] read per n16-tile via LDG (L1-hot), no smem reduction needed.
#define GEMM_SMEM (3 * 32768)

__device__ __forceinline__ void issue_quarter(uint32_t sb, int tid, int kg, int qq) {
    int k = kg * KPC + (qq >> 2);
    int q = qq & 3;
    const char* src = reinterpret_cast<const char*>(g_Sbf) + (size_t)k * 131072 + (size_t)q * 32768;
    uint32_t base = sb + (uint32_t)(qq % 3) * 32768u;
    #pragma unroll
    for (int j = 0; j < 8; j++) {
        int i = tid + j * 256;
        int row = i >> 5;                       // 0..63 e-rows
        uint32_t colb = (uint32_t)(i & 31) * 16u;  // 0..496
        uint32_t dst = base + (uint32_t)row * 512u + (colb & 0xFFFFFF80u)
                     + ((colb & 127u) ^ (((uint32_t)row & 7u) << 4));
        cp_async16(dst, src + (size_t)row * 512 + colb);
    }
}

__global__ void __launch_bounds__(256, 1)
gemm_loss_kernel(const int* __restrict__ y) {
    extern __shared__ char smem[];
    uint32_t sb = smem_to_u32(smem);
    int tid = threadIdx.x, wid = tid >> 5, lid = tid & 31;
    int bt = blockIdx.x, kg = blockIdx.y;
    int Rw = bt * 256 + wid * 32;           // warp's 32 batch rows
    int gq = lid >> 2, cq = lid & 3;
    int lrow = lid & 15;
    uint32_t lcb16 = (uint32_t)(lid >> 4) * 16u;

    // prologue: start the ring
    issue_quarter(sb, tid, kg, 0); CP_COMMIT();
    issue_quarter(sb, tid, kg, 1); CP_COMMIT();
    issue_quarter(sb, tid, kg, 2); CP_COMMIT();

    // A fragments in registers: afr[mt][s][0..3] for mma.m16n8k16
    // a0 = x[r0+gq, 2cq..2cq+1 of k16-step s], a1 = row+8, a2 = cols+8, a3 = row+8 cols+8
    uint32_t afr[2][16][4];
    #pragma unroll
    for (int mt = 0; mt < 2; mt++) {
        int r0 = Rw + mt * 16 + gq;
        const uint32_t* p0 = reinterpret_cast<const uint32_t*>(g_Xbf + (size_t)r0 * 256);
        const uint32_t* p1 = reinterpret_cast<const uint32_t*>(g_Xbf + (size_t)(r0 + 8) * 256);
        #pragma unroll
        for (int s = 0; s < 16; s++) {
            afr[mt][s][0] = p0[8 * s + cq];
            afr[mt][s][1] = p1[8 * s + cq];
            afr[mt][s][2] = p0[8 * s + cq + 4];
            afr[mt][s][3] = p1[8 * s + cq + 4];
        }
    }

    float rs[2][2]   = {{0.f, 0.f}, {0.f, 0.f}};   // xSx partial (current k)
    float rsum[2][2] = {{0.f, 0.f}, {0.f, 0.f}};   // loss partial (over KPC k's)

    for (int qq = 0; qq < QPC; qq++) {
        CP_WAIT(2);              // exactly quarter qq's group done (constant lead of 2)
        __syncthreads();
        uint32_t qbase = sb + (uint32_t)(qq % 3) * 32768u;
        int q = qq & 3;

        #pragma unroll
        for (int t = 0; t < 4; t++) {
            int ebase = q * 64 + t * 16;
            // contraction weights x[row, e] for this n16 tile (L1-hot LDGs)
            uint32_t w[2][4];
            #pragma unroll
            for (int mt = 0; mt < 2; mt++) {
                int r0 = Rw + mt * 16 + gq;
                const uint32_t* q0 = reinterpret_cast<const uint32_t*>(g_Xbf + (size_t)r0 * 256 + ebase);
                const uint32_t* q1 = reinterpret_cast<const uint32_t*>(g_Xbf + (size_t)(r0 + 8) * 256 + ebase);
                w[mt][0] = q0[cq];        // row gq,   e = ebase+2cq
                w[mt][1] = q0[cq + 4];    // row gq,   e = ebase+8+2cq
                w[mt][2] = q1[cq];        // row gq+8, e = ebase+2cq
                w[mt][3] = q1[cq + 4];    // row gq+8, e = ebase+8+2cq
            }
            float acc[2][2][4];
            #pragma unroll
            for (int mt = 0; mt < 2; mt++)
                #pragma unroll
                for (int n = 0; n < 2; n++)
                    #pragma unroll
                    for (int f = 0; f < 4; f++) acc[mt][n][f] = 0.f;

            uint32_t rowa = (uint32_t)(t * 16 + lrow);
            uint32_t rbase = qbase + rowa * 512u;
            uint32_t rxor = (rowa & 7u) << 4;
            #pragma unroll
            for (int s = 0; s < 16; s++) {
                uint32_t colb = 32u * (uint32_t)s + lcb16;
                uint32_t addr = rbase + (colb & 0xFFFFFF80u) + ((colb & 127u) ^ rxor);
                uint32_t b0, b1, b2, b3;
                ldsm_x4(b0, b1, b2, b3, addr);
                #pragma unroll
                for (int mt = 0; mt < 2; mt++) {
                    mma_bf16(acc[mt][0], afr[mt][s], b0, b2);
                    mma_bf16(acc[mt][1], afr[mt][s], b1, b3);
                }
            }
            // contract this n16 tile into scalars (weights from registers)
            #pragma unroll
            for (int mt = 0; mt < 2; mt++) {
                float2 v;
                v = __bfloat1622float2(*reinterpret_cast<__nv_bfloat162*>(&w[mt][0]));
                rs[mt][0] = fmaf(acc[mt][0][0], v.x, fmaf(acc[mt][0][1], v.y, rs[mt][0]));
                v = __bfloat1622float2(*reinterpret_cast<__nv_bfloat162*>(&w[mt][1]));
                rs[mt][0] = fmaf(acc[mt][1][0], v.x, fmaf(acc[mt][1][1], v.y, rs[mt][0]));
                v = __bfloat1622float2(*reinterpret_cast<__nv_bfloat162*>(&w[mt][2]));
                rs[mt][1] = fmaf(acc[mt][0][2], v.x, fmaf(acc[mt][0][3], v.y, rs[mt][1]));
                v = __bfloat1622float2(*reinterpret_cast<__nv_bfloat162*>(&w[mt][3]));
                rs[mt][1] = fmaf(acc[mt][1][2], v.x, fmaf(acc[mt][1][3], v.y, rs[mt][1]));
            }
        }
        __syncthreads();         // all warps done with this ring buffer
        if (qq + 3 < QPC) issue_quarter(sb, tid, kg, qq + 3);
        CP_COMMIT();             // always commit (possibly empty) -> constant group lead

        if ((qq & 3) == 3) {     // finished all e for this k: loss epilogue
            int k = kg * KPC + (qq >> 2);
            #pragma unroll
            for (int mt = 0; mt < 2; mt++)
                #pragma unroll
                for (int h = 0; h < 2; h++) {
                    float v = rs[mt][h];
                    v += __shfl_xor_sync(0xFFFFFFFF, v, 1);
                    v += __shfl_xor_sync(0xFFFFFFFF, v, 2);
                    rs[mt][h] = v;
                }
            if (cq == 0) {
                #pragma unroll
                for (int mt = 0; mt < 2; mt++)
                    #pragma unroll
                    for (int h = 0; h < 2; h++) {
                        int b = Rw + mt * 16 + gq + h * 8;
                        float l = g_logits[(size_t)b * KK + k];
                        int yv = y[b];
                        float psi = sqrtf(fmaxf(rs[mt][h], 0.f) + l * l);
                        float bk  = (k <= yv) ? 1.f : 0.f;
                        float kap = ((k == yv) ? 1.f : 0.f) - 0.5f * bk;
                        float sp  = psi + log1pf(__expf(-psi));   // softplus(psi), psi>=0
                        rsum[mt][h] += l * kap + bk * (0.5f * psi - sp);
                    }
            }
            rs[0][0] = rs[0][1] = rs[1][0] = rs[1][1] = 0.f;
        }
    }

    if (cq == 0) {
        #pragma unroll
        for (int mt = 0; mt < 2; mt++)
            #pragma unroll
            for (int h = 0; h < 2; h++) {
                int b = Rw + mt * 16 + gq + h * 8;
                g_contrib[(size_t)kg * BB + b] = rsum[mt][h];
            }
    }
}

// ---------------- kernel 4: deterministic reduce over kg slices ----------------
__global__ void reduce_kernel(float* __restrict__ out) {
    int b = blockIdx.x * blockDim.x + threadIdx.x;
    if (b < BB) {
        float s = 0.f;
        #pragma unroll
        for (int kgi = 0; kgi < KK / KPC; kgi++) s += g_contrib[(size_t)kgi * BB + b];
        out[b] = -s;
    }
}

// ---------------- launch ----------------
extern "C" void kernel_launch(void* const* d_in, const int* in_sizes, int n_in,
                              void* d_out, int out_size) {
    (void)in_sizes; (void)n_in; (void)out_size;
    const float* features = (const float*)d_in[0];
    const int*   y        = (const int*)d_in[1];
    const float* mu       = (const float*)d_in[2];
    const float* Sigma    = (const float*)d_in[3];
    float* out = (float*)d_out;

    cudaFuncSetAttribute(logits_kernel,    cudaFuncAttributeMaxDynamicSharedMemorySize, LOGITS_SMEM);
    cudaFuncSetAttribute(gemm_loss_kernel, cudaFuncAttributeMaxDynamicSharedMemorySize, GEMM_SMEM);

    conv_kernel<<<(NX4 + NS4 + 255) / 256, 256>>>(
        reinterpret_cast<const float4*>(features),
        reinterpret_cast<const float4*>(Sigma));
    logits_kernel<<<BB / 128, 256, LOGITS_SMEM>>>(features, mu);
    dim3 grid(BB / 256, KK / KPC);
    gemm_loss_kernel<<<grid, 256, GEMM_SMEM>>>(y);
    reduce_kernel<<<BB / 128, 128>>>(out);
}

// round 6
// speedup vs baseline: 1.1261x; 1.0031x over previous
#include <cuda_runtime.h>
#include <cuda_bf16.h>
#include <cstdint>

// Problem constants (fixed shapes)
#define BB 8192
#define DD 256
#define KK 64
#define KPC 2            // k's per CTA
#define QPC (KPC * 4)    // quarters per CTA (4 e-quarters per k)

// ---------------- scratch (static device arrays; no allocation) ----------------
__device__ __nv_bfloat16 g_Xbf[BB * DD];          // 4 MB
__device__ __nv_bfloat16 g_Sbf[KK * DD * DD];     // 8.4 MB
__device__ float         g_logits[BB * KK];       // 2 MB
__device__ float         g_contrib[(KK / KPC) * BB];  // 1 MB (32 slices)

// ---------------- helpers ----------------
__device__ __forceinline__ uint32_t smem_to_u32(const void* p) {
    uint32_t a;
    asm("{ .reg .u64 t; cvta.to.shared.u64 t, %1; cvt.u32.u64 %0, t; }" : "=r"(a) : "l"(p));
    return a;
}

__device__ __forceinline__ void cp_async16(uint32_t dst, const void* src) {
    asm volatile("cp.async.cg.shared.global [%0], [%1], 16;" :: "r"(dst), "l"(src));
}
#define CP_COMMIT() asm volatile("cp.async.commit_group;" ::: "memory")
#define CP_WAIT(n)  asm volatile("cp.async.wait_group %0;" :: "n"(n) : "memory")

__device__ __forceinline__ void ldsm_x4(uint32_t& r0, uint32_t& r1, uint32_t& r2, uint32_t& r3,
                                        uint32_t addr) {
    asm volatile("ldmatrix.sync.aligned.m8n8.x4.shared.b16 {%0,%1,%2,%3}, [%4];"
                 : "=r"(r0), "=r"(r1), "=r"(r2), "=r"(r3) : "r"(addr));
}

__device__ __forceinline__ void mma_bf16(float* d, const uint32_t* a, uint32_t b0, uint32_t b1) {
    asm volatile(
        "mma.sync.aligned.m16n8k16.row.col.f32.bf16.bf16.f32 "
        "{%0,%1,%2,%3}, {%4,%5,%6,%7}, {%8,%9}, {%0,%1,%2,%3};"
        : "+f"(d[0]), "+f"(d[1]), "+f"(d[2]), "+f"(d[3])
        : "r"(a[0]), "r"(a[1]), "r"(a[2]), "r"(a[3]), "r"(b0), "r"(b1));
}

// ---------------- kernel 1: fused fp32 -> bf16 converts (X then Sigma) ----------------
#define NX4 (BB * DD / 4)              // 524288 float4s for X
#define NS4 (KK * DD * DD / 4)         // 1048576 float4s for Sigma
__global__ void conv_kernel(const float4* __restrict__ xsrc, const float4* __restrict__ ssrc) {
    int i = blockIdx.x * blockDim.x + threadIdx.x;
    if (i < NX4) {
        float4 v = xsrc[i];
        __nv_bfloat162* dst = reinterpret_cast<__nv_bfloat162*>(g_Xbf);
        dst[2 * i]     = __floats2bfloat162_rn(v.x, v.y);
        dst[2 * i + 1] = __floats2bfloat162_rn(v.z, v.w);
    } else if (i < NX4 + NS4) {
        int j = i - NX4;
        float4 v = ssrc[j];
        __nv_bfloat162* dst = reinterpret_cast<__nv_bfloat162*>(g_Sbf);
        dst[2 * j]     = __floats2bfloat162_rn(v.x, v.y);
        dst[2 * j + 1] = __floats2bfloat162_rn(v.z, v.w);
    }
}

// ---------------- kernel 2: logits = X @ mu (fp32, exact) ----------------
#define LOGITS_SMEM ((128 * 257 + 256 * 64) * 4)
__global__ void logits_kernel(const float* __restrict__ X, const float* __restrict__ mu) {
    extern __shared__ float sm[];
    float* xs  = sm;                // [128][257] padded
    float* mus = sm + 128 * 257;    // [256][64]
    int t = threadIdx.x;
    int b0 = blockIdx.x * 128;

    const float4* xg = reinterpret_cast<const float4*>(X + (size_t)b0 * DD);
    #pragma unroll
    for (int j = 0; j < 32; j++) {
        int i = t + j * 256;
        float4 v = xg[i];
        int r = i >> 6, c = (i & 63) << 2;
        float* p = xs + r * 257 + c;
        p[0] = v.x; p[1] = v.y; p[2] = v.z; p[3] = v.w;
    }
    const float4* mg = reinterpret_cast<const float4*>(mu);
    float4* ms4 = reinterpret_cast<float4*>(mus);
    #pragma unroll
    for (int j = 0; j < 16; j++) ms4[t + j * 256] = mg[t + j * 256];
    __syncthreads();

    int r = t & 127;
    int kh = (t >> 7) * 32;
    float acc[32];
    #pragma unroll
    for (int kk = 0; kk < 32; kk++) acc[kk] = 0.f;
    const float* xr = xs + r * 257;
    for (int d = 0; d < DD; d++) {
        float xv = xr[d];
        const float* mrow = mus + d * 64 + kh;
        #pragma unroll
        for (int kk = 0; kk < 32; kk++) acc[kk] = fmaf(xv, mrow[kk], acc[kk]);
    }
    float* og = g_logits + (size_t)(b0 + r) * KK + kh;
    #pragma unroll
    for (int kk = 0; kk < 32; kk++) og[kk] = acc[kk];
}

// ---------------- kernel 3: main GEMM (A in registers, B 4-deep quarter ring) + loss ----------------
// grid (32 b-tiles, 32 kg), 256 threads (8 warps, each warp m32 over ALL e).
// Inner loop processes TWO n16-tiles concurrently -> 8 independent HMMA chains/warp.
#define GEMM_SMEM (4 * 32768)

__device__ __forceinline__ void issue_quarter(uint32_t sb, int tid, int kg, int qq) {
    int k = kg * KPC + (qq >> 2);
    int q = qq & 3;
    const char* src = reinterpret_cast<const char*>(g_Sbf) + (size_t)k * 131072 + (size_t)q * 32768;
    uint32_t base = sb + (uint32_t)(qq & 3) * 32768u;
    #pragma unroll
    for (int j = 0; j < 8; j++) {
        int i = tid + j * 256;
        int row = i >> 5;                          // 0..63 e-rows
        uint32_t colb = (uint32_t)(i & 31) * 16u;  // 0..496
        uint32_t dst = base + (uint32_t)row * 512u + (colb & 0xFFFFFF80u)
                     + ((colb & 127u) ^ (((uint32_t)row & 7u) << 4));
        cp_async16(dst, src + (size_t)row * 512 + colb);
    }
}

__global__ void __launch_bounds__(256, 1)
gemm_loss_kernel(const int* __restrict__ y) {
    extern __shared__ char smem[];
    uint32_t sb = smem_to_u32(smem);
    int tid = threadIdx.x, wid = tid >> 5, lid = tid & 31;
    int bt = blockIdx.x, kg = blockIdx.y;
    int Rw = bt * 256 + wid * 32;           // warp's 32 batch rows
    int gq = lid >> 2, cq = lid & 3;
    int lrow = lid & 15;
    uint32_t lcb16 = (uint32_t)(lid >> 4) * 16u;

    // prologue: start the ring (quarters 0,1,2 in buffers 0,1,2)
    issue_quarter(sb, tid, kg, 0); CP_COMMIT();
    issue_quarter(sb, tid, kg, 1); CP_COMMIT();
    issue_quarter(sb, tid, kg, 2); CP_COMMIT();

    // A fragments in registers: afr[mt][s][0..3] for mma.m16n8k16
    uint32_t afr[2][16][4];
    #pragma unroll
    for (int mt = 0; mt < 2; mt++) {
        int r0 = Rw + mt * 16 + gq;
        const uint32_t* p0 = reinterpret_cast<const uint32_t*>(g_Xbf + (size_t)r0 * 256);
        const uint32_t* p1 = reinterpret_cast<const uint32_t*>(g_Xbf + (size_t)(r0 + 8) * 256);
        #pragma unroll
        for (int s = 0; s < 16; s++) {
            afr[mt][s][0] = p0[8 * s + cq];
            afr[mt][s][1] = p1[8 * s + cq];
            afr[mt][s][2] = p0[8 * s + cq + 4];
            afr[mt][s][3] = p1[8 * s + cq + 4];
        }
    }

    float rs[2][2]   = {{0.f, 0.f}, {0.f, 0.f}};   // xSx partial (current k)
    float rsum[2][2] = {{0.f, 0.f}, {0.f, 0.f}};   // loss partial (over KPC k's)

    #pragma unroll 1
    for (int qq = 0; qq < QPC; qq++) {
        // prefetch quarter qq+3 into buffer (qq+3)&3 (distinct from current qq&3)
        if (qq + 3 < QPC) { issue_quarter(sb, tid, kg, qq + 3); CP_COMMIT(); }
        // exact wait: number of (non-empty) groups newer than quarter qq
        if      (qq <= QPC - 4) CP_WAIT(3);
        else if (qq == QPC - 3) CP_WAIT(2);
        else if (qq == QPC - 2) CP_WAIT(1);
        else                    CP_WAIT(0);
        __syncthreads();

        uint32_t qbase = sb + (uint32_t)(qq & 3) * 32768u;
        int q = qq & 3;

        #pragma unroll
        for (int tp = 0; tp < 2; tp++) {
            int t0 = tp * 2;
            int ebase0 = q * 64 + t0 * 16;
            // contraction weights x[row, e] for both tiles (L1-hot LDGs)
            uint32_t w[2][2][4];   // [tile][mt][frag]
            #pragma unroll
            for (int mt = 0; mt < 2; mt++) {
                int r0 = Rw + mt * 16 + gq;
                const uint32_t* q0 = reinterpret_cast<const uint32_t*>(g_Xbf + (size_t)r0 * 256 + ebase0);
                const uint32_t* q1 = reinterpret_cast<const uint32_t*>(g_Xbf + (size_t)(r0 + 8) * 256 + ebase0);
                #pragma unroll
                for (int tt = 0; tt < 2; tt++) {
                    w[tt][mt][0] = q0[tt * 8 + cq];
                    w[tt][mt][1] = q0[tt * 8 + cq + 4];
                    w[tt][mt][2] = q1[tt * 8 + cq];
                    w[tt][mt][3] = q1[tt * 8 + cq + 4];
                }
            }
            float acc[2][2][2][4];   // [tile][mt][n8][frag]
            #pragma unroll
            for (int tt = 0; tt < 2; tt++)
                #pragma unroll
                for (int mt = 0; mt < 2; mt++)
                    #pragma unroll
                    for (int n = 0; n < 2; n++)
                        #pragma unroll
                        for (int f = 0; f < 4; f++) acc[tt][mt][n][f] = 0.f;

            uint32_t rowa0 = (uint32_t)(t0 * 16 + lrow);
            uint32_t rbase0 = qbase + rowa0 * 512u;
            uint32_t rbase1 = rbase0 + 16u * 512u;
            uint32_t rxor = (rowa0 & 7u) << 4;      // same for row+16
            #pragma unroll
            for (int s = 0; s < 16; s++) {
                uint32_t colb = 32u * (uint32_t)s + lcb16;
                uint32_t coff = (colb & 0xFFFFFF80u) + ((colb & 127u) ^ rxor);
                uint32_t b00, b01, b02, b03, b10, b11, b12, b13;
                ldsm_x4(b00, b01, b02, b03, rbase0 + coff);
                ldsm_x4(b10, b11, b12, b13, rbase1 + coff);
                // 8 independent accumulator chains
                mma_bf16(acc[0][0][0], afr[0][s], b00, b02);
                mma_bf16(acc[0][1][0], afr[1][s], b00, b02);
                mma_bf16(acc[1][0][0], afr[0][s], b10, b12);
                mma_bf16(acc[1][1][0], afr[1][s], b10, b12);
                mma_bf16(acc[0][0][1], afr[0][s], b01, b03);
                mma_bf16(acc[0][1][1], afr[1][s], b01, b03);
                mma_bf16(acc[1][0][1], afr[0][s], b11, b13);
                mma_bf16(acc[1][1][1], afr[1][s], b11, b13);
            }
            // contract both tiles into scalars
            #pragma unroll
            for (int tt = 0; tt < 2; tt++)
                #pragma unroll
                for (int mt = 0; mt < 2; mt++) {
                    float2 v;
                    v = __bfloat1622float2(*reinterpret_cast<__nv_bfloat162*>(&w[tt][mt][0]));
                    rs[mt][0] = fmaf(acc[tt][mt][0][0], v.x, fmaf(acc[tt][mt][0][1], v.y, rs[mt][0]));
                    v = __bfloat1622float2(*reinterpret_cast<__nv_bfloat162*>(&w[tt][mt][1]));
                    rs[mt][0] = fmaf(acc[tt][mt][1][0], v.x, fmaf(acc[tt][mt][1][1], v.y, rs[mt][0]));
                    v = __bfloat1622float2(*reinterpret_cast<__nv_bfloat162*>(&w[tt][mt][2]));
                    rs[mt][1] = fmaf(acc[tt][mt][0][2], v.x, fmaf(acc[tt][mt][0][3], v.y, rs[mt][1]));
                    v = __bfloat1622float2(*reinterpret_cast<__nv_bfloat162*>(&w[tt][mt][3]));
                    rs[mt][1] = fmaf(acc[tt][mt][1][2], v.x, fmaf(acc[tt][mt][1][3], v.y, rs[mt][1]));
                }
        }
        __syncthreads();         // all warps done with this ring buffer

        if ((qq & 3) == 3) {     // finished all e for this k: loss epilogue
            int k = kg * KPC + (qq >> 2);
            #pragma unroll
            for (int mt = 0; mt < 2; mt++)
                #pragma unroll
                for (int h = 0; h < 2; h++) {
                    float v = rs[mt][h];
                    v += __shfl_xor_sync(0xFFFFFFFF, v, 1);
                    v += __shfl_xor_sync(0xFFFFFFFF, v, 2);
                    rs[mt][h] = v;
                }
            if (cq == 0) {
                #pragma unroll
                for (int mt = 0; mt < 2; mt++)
                    #pragma unroll
                    for (int h = 0; h < 2; h++) {
                        int b = Rw + mt * 16 + gq + h * 8;
                        float l = g_logits[(size_t)b * KK + k];
                        int yv = y[b];
                        float psi = sqrtf(fmaxf(rs[mt][h], 0.f) + l * l);
                        float bk  = (k <= yv) ? 1.f : 0.f;
                        float kap = ((k == yv) ? 1.f : 0.f) - 0.5f * bk;
                        float sp  = psi + log1pf(__expf(-psi));   // softplus(psi), psi>=0
                        rsum[mt][h] += l * kap + bk * (0.5f * psi - sp);
                    }
            }
            rs[0][0] = rs[0][1] = rs[1][0] = rs[1][1] = 0.f;
        }
    }

    if (cq == 0) {
        #pragma unroll
        for (int mt = 0; mt < 2; mt++)
            #pragma unroll
            for (int h = 0; h < 2; h++) {
                int b = Rw + mt * 16 + gq + h * 8;
                g_contrib[(size_t)kg * BB + b] = rsum[mt][h];
            }
    }
}

// ---------------- kernel 4: deterministic reduce over kg slices ----------------
__global__ void reduce_kernel(float* __restrict__ out) {
    int b = blockIdx.x * blockDim.x + threadIdx.x;
    if (b < BB) {
        float s = 0.f;
        #pragma unroll
        for (int kgi = 0; kgi < KK / KPC; kgi++) s += g_contrib[(size_t)kgi * BB + b];
        out[b] = -s;
    }
}

// ---------------- launch ----------------
extern "C" void kernel_launch(void* const* d_in, const int* in_sizes, int n_in,
                              void* d_out, int out_size) {
    (void)in_sizes; (void)n_in; (void)out_size;
    const float* features = (const float*)d_in[0];
    const int*   y        = (const int*)d_in[1];
    const float* mu       = (const float*)d_in[2];
    const float* Sigma    = (const float*)d_in[3];
    float* out = (float*)d_out;

    cudaFuncSetAttribute(logits_kernel,    cudaFuncAttributeMaxDynamicSharedMemorySize, LOGITS_SMEM);
    cudaFuncSetAttribute(gemm_loss_kernel, cudaFuncAttributeMaxDynamicSharedMemorySize, GEMM_SMEM);

    conv_kernel<<<(NX4 + NS4 + 255) / 256, 256>>>(
        reinterpret_cast<const float4*>(features),
        reinterpret_cast<const float4*>(Sigma));
    logits_kernel<<<BB / 128, 256, LOGITS_SMEM>>>(features, mu);
    dim3 grid(BB / 256, KK / KPC);
    gemm_loss_kernel<<<grid, 256, GEMM_SMEM>>>(y);
    reduce_kernel<<<BB / 128, 128>>>(out);
}